// round 5
// baseline (speedup 1.0000x reference)
#include <cuda_runtime.h>

// LeakyCascade: s[t] = a*s[t-1] + (1-a)*x[t] = a*(s-x)+x,  a = exp(-dt/tau_m)
// B=8, T=4096, D=256, M=8.
// Blocked scan over T. Block = 128 threads = 2 m-groups x 64 d-lanes; each
// thread owns 4 m-states (float4 each) in registers. CC=256 chunks -> 2048
// blocks for high occupancy.

#define BB 8
#define TT 4096
#define DD 256
#define MM 8
#define CC 256           // chunks along T
#define LL (TT / CC)     // 16 steps per chunk
#define D4 (DD / 4)      // 64 float4 lanes
#define MG 2             // m-groups per block
#define MPT (MM / MG)    // 4 m-states per thread
#define NTHR (MG * D4)   // 128 threads

// Scratch (static device globals — no allocation anywhere)
// Layout [B][C][M][D]: phase2 (thread=(b,m,d)) reads coalesced in d.
__device__ float g_send[BB * CC * MM * DD];  // local chunk end-states (16 MB)
__device__ float g_sin [BB * CC * MM * DD];  // true chunk start-states (16 MB)
__device__ float g_A   [BB * CC * MM];       // per-chunk total decay

// ---------------------------------------------------------------------------
// Alpha staging for one chunk: sdt[i], sal[m][i], sdsum.
// 128 threads: threads 0..15 build dt; then each thread does ONE expf.
// ---------------------------------------------------------------------------
__device__ __forceinline__ void stage_alpha(
    const float* __restrict__ drow, const float* __restrict__ tau,
    int tid, int t0, float* sdt, float (*sal)[LL], float* sdsum)
{
    if (tid < LL) {
        const int t = t0 + tid;
        float dt = (t == 0) ? 0.0f : fmaxf(drow[t] - drow[t - 1], 0.0f);
        sdt[tid] = dt;
        float dsum = dt;
        #pragma unroll
        for (int off = LL / 2; off > 0; off >>= 1)
            dsum += __shfl_down_sync(0x0000ffffu, dsum, off);
        if (tid == 0) *sdsum = dsum;
    }
    __syncthreads();
    // MM*LL == NTHR: one alpha per thread.
    sal[tid >> 4][tid & (LL - 1)] = expf(-sdt[tid & (LL - 1)] / tau[tid >> 4]);
    __syncthreads();
}

// ---------------------------------------------------------------------------
// Phase 1: per-chunk local scan from s=0; emit s_end and chunk decay A.
// grid = (CC, B) = (256, 8), block = 128
// ---------------------------------------------------------------------------
__global__ void __launch_bounds__(NTHR) lc_phase1(
    const float* __restrict__ x, const float* __restrict__ delta,
    const float* __restrict__ tau)
{
    const int c = blockIdx.x, b = blockIdx.y;
    const int tid  = threadIdx.x;
    const int mg   = tid >> 6;        // m-group: 0 or 1
    const int lane = tid & 63;        // d-lane (float4)
    const int m0   = mg * MPT;
    const int t0   = c * LL;

    __shared__ float sdt[LL];
    __shared__ float sal[MM][LL];
    __shared__ float sdsum;

    stage_alpha(delta + b * TT, tau, tid, t0, sdt, sal, &sdsum);

    float4 s[MPT];
    #pragma unroll
    for (int j = 0; j < MPT; j++) s[j] = make_float4(0.f, 0.f, 0.f, 0.f);

    const float4* xp = (const float4*)x + (b * TT + t0) * D4 + lane;
    #pragma unroll
    for (int i = 0; i < LL; i++) {
        const float4 xv = xp[i * D4];
        #pragma unroll
        for (int j = 0; j < MPT; j++) {
            const float a = sal[m0 + j][i];
            s[j].x = fmaf(a, s[j].x - xv.x, xv.x);
            s[j].y = fmaf(a, s[j].y - xv.y, xv.y);
            s[j].z = fmaf(a, s[j].z - xv.z, xv.z);
            s[j].w = fmaf(a, s[j].w - xv.w, xv.w);
        }
    }

    const int base = ((b * CC + c) * MM + m0) * D4 + lane;
    #pragma unroll
    for (int j = 0; j < MPT; j++)
        ((float4*)g_send)[base + j * D4] = s[j];
    if (tid < MM)
        g_A[(b * CC + c) * MM + tid] = expf(-sdsum / tau[tid]);
}

// ---------------------------------------------------------------------------
// Phase 2: sequential scan across chunks per (b,m,d):
//   s_in[c] = s;  s = A[c]*s + s_end[c].   Scratch is L2-resident.
// 16384 threads, coalesced in d.
// ---------------------------------------------------------------------------
__global__ void __launch_bounds__(128) lc_phase2()
{
    const int idx = blockIdx.x * blockDim.x + threadIdx.x;  // (b*M+m)*D + d
    const int d  = idx % DD;
    const int bm = idx / DD;
    const int m  = bm % MM;
    const int b  = bm / MM;

    const float* Ap = g_A + (b * CC) * MM + m;
    float* sendp = g_send + ((b * CC) * MM + m) * DD + d;
    float* sinp  = g_sin  + ((b * CC) * MM + m) * DD + d;

    float s = 0.0f;
    #pragma unroll 8
    for (int c = 0; c < CC; c++) {
        sinp[c * (MM * DD)] = s;
        s = fmaf(Ap[c * MM], s, sendp[c * (MM * DD)]);
    }
}

// ---------------------------------------------------------------------------
// Phase 3: re-scan each chunk from its true s_in and stream the output.
// Per t-step a block stores one contiguous 8KB (t,:,:) row (STG.128).
// ---------------------------------------------------------------------------
__global__ void __launch_bounds__(NTHR) lc_phase3(
    const float* __restrict__ x, const float* __restrict__ delta,
    const float* __restrict__ tau, float* __restrict__ out)
{
    const int c = blockIdx.x, b = blockIdx.y;
    const int tid  = threadIdx.x;
    const int mg   = tid >> 6;
    const int lane = tid & 63;
    const int m0   = mg * MPT;
    const int t0   = c * LL;

    __shared__ float sdt[LL];
    __shared__ float sal[MM][LL];
    __shared__ float sdsum;

    stage_alpha(delta + b * TT, tau, tid, t0, sdt, sal, &sdsum);

    const int base = ((b * CC + c) * MM + m0) * D4 + lane;
    float4 s[MPT];
    #pragma unroll
    for (int j = 0; j < MPT; j++)
        s[j] = ((const float4*)g_sin)[base + j * D4];

    const float4* xp = (const float4*)x + (b * TT + t0) * D4 + lane;
    float4* op = (float4*)out + (b * TT + t0) * (MM * D4) + m0 * D4 + lane;

    #pragma unroll
    for (int i = 0; i < LL; i++) {
        const float4 xv = xp[i * D4];
        #pragma unroll
        for (int j = 0; j < MPT; j++) {
            const float a = sal[m0 + j][i];
            s[j].x = fmaf(a, s[j].x - xv.x, xv.x);
            s[j].y = fmaf(a, s[j].y - xv.y, xv.y);
            s[j].z = fmaf(a, s[j].z - xv.z, xv.z);
            s[j].w = fmaf(a, s[j].w - xv.w, xv.w);
        }
        float4* orow = op + i * (MM * D4);
        #pragma unroll
        for (int j = 0; j < MPT; j++)
            orow[j * D4] = s[j];
    }
}

// ---------------------------------------------------------------------------
extern "C" void kernel_launch(void* const* d_in, const int* in_sizes, int n_in,
                              void* d_out, int out_size)
{
    const float* x     = (const float*)d_in[0];
    const float* delta = (const float*)d_in[1];
    const float* tau   = (const float*)d_in[2];
    float* out = (float*)d_out;

    dim3 grid(CC, BB);
    lc_phase1<<<grid, NTHR>>>(x, delta, tau);
    lc_phase2<<<128, 128>>>();
    lc_phase3<<<grid, NTHR>>>(x, delta, tau, out);
}